// round 1
// baseline (speedup 1.0000x reference)
#include <cuda_runtime.h>
#include <cuda_bf16.h>
#include <cstdint>

// Problem dims
#define S_LEN 1024
#define BATCH 64
#define IDIM  512
#define HDIM  2048
#define ODIM  512
#define MTOT  (S_LEN * BATCH)   // 65536

// ---------------------------------------------------------------------------
// Device scratch (no cudaMalloc allowed)
// ---------------------------------------------------------------------------
__device__ float g_Xc[(size_t)MTOT * IDIM];        // 128 MB  tf32-rounded X
__device__ float g_Wc[(size_t)HDIM * IDIM];        // 4 MB    tf32-rounded W_ih
__device__ float g_u [(size_t)MTOT * HDIM];        // 512 MB  u[s*64+b][h]
__device__ float g_h [(size_t)BATCH * HDIM];       // 512 KB  h_final[b][h]
__device__ float g_part[(size_t)16 * BATCH * ODIM];// 2 MB    split-K partials

// ---------------------------------------------------------------------------
// Helpers
// ---------------------------------------------------------------------------
__device__ __forceinline__ float to_tf32(float x) {
    uint32_t r;
    asm("cvt.rna.tf32.f32 %0, %1;" : "=r"(r) : "f"(x));
    return __uint_as_float(r);
}

__device__ __forceinline__ void cp_async16(uint32_t saddr, const void* gptr) {
    asm volatile("cp.async.cg.shared.global [%0], [%1], 16;\n"
                 :: "r"(saddr), "l"(gptr) : "memory");
}
#define CP_COMMIT() asm volatile("cp.async.commit_group;\n" ::: "memory")
#define CP_WAIT(N)  asm volatile("cp.async.wait_group %0;\n" :: "n"(N) : "memory")

// ---------------------------------------------------------------------------
// Kernel 1a/1b: round inputs to tf32 (rna) once, so the GEMM inner loop has
// no cvt instructions competing with HMMA issue.
// ---------------------------------------------------------------------------
__global__ void cvtX_kernel(const float4* __restrict__ X) {
    int i = blockIdx.x * blockDim.x + threadIdx.x;   // MTOT*IDIM/4 threads
    float4 v = X[i];
    v.x = to_tf32(v.x); v.y = to_tf32(v.y);
    v.z = to_tf32(v.z); v.w = to_tf32(v.w);
    reinterpret_cast<float4*>(g_Xc)[i] = v;
}

__global__ void cvtW_kernel(const float4* __restrict__ W) {
    int i = blockIdx.x * blockDim.x + threadIdx.x;   // HDIM*IDIM/4 threads
    float4 v = W[i];
    v.x = to_tf32(v.x); v.y = to_tf32(v.y);
    v.z = to_tf32(v.z); v.w = to_tf32(v.w);
    reinterpret_cast<float4*>(g_Wc)[i] = v;
}

// ---------------------------------------------------------------------------
// Kernel 2: u = Xc @ Wc^T via mma.sync.m16n8k8 tf32 (fp32 accumulate).
// CTA tile 128x128, BK=16, cp.async double buffer, 8 warps (4x2),
// warp tile 32x64, per-warp 2x8 m16n8 frags.
// ---------------------------------------------------------------------------
#define BM 128
#define BN 128
#define BK 16
#define KTILES (IDIM / BK)   // 32
#define LDA (BK + 4)         // 20 floats, conflict-free pattern
#define STAGE_BYTES (BM * LDA * 4)   // 10240

__global__ __launch_bounds__(256) void gemm_u_kernel() {
    __shared__ float sA[2][BM * LDA];
    __shared__ float sB[2][BN * LDA];

    const int tid  = threadIdx.x;
    const int lane = tid & 31;
    const int warp = tid >> 5;
    const int wm   = warp >> 1;   // 0..3
    const int wn   = warp & 1;    // 0..1
    const int g    = lane >> 2;   // 0..7
    const int tg   = lane & 3;    // 0..3

    const int m0 = blockIdx.y * BM;
    const int n0 = blockIdx.x * BN;

    const uint32_t sA_base = (uint32_t)__cvta_generic_to_shared(&sA[0][0]);
    const uint32_t sB_base = (uint32_t)__cvta_generic_to_shared(&sB[0][0]);

    float c[2][8][4];
#pragma unroll
    for (int mi = 0; mi < 2; mi++)
#pragma unroll
        for (int ni = 0; ni < 8; ni++)
#pragma unroll
            for (int r = 0; r < 4; r++) c[mi][ni][r] = 0.0f;

    // tile loaders: 128 rows x 16 floats = 512 float4 / 256 thr = 2 each
    auto loadA = [&](int stage, int kt) {
#pragma unroll
        for (int i = 0; i < 2; i++) {
            int lin = tid + i * 256;
            int row = lin >> 2, c4 = lin & 3;
            cp_async16(sA_base + stage * STAGE_BYTES + (row * LDA + c4 * 4) * 4,
                       g_Xc + (size_t)(m0 + row) * IDIM + kt * BK + c4 * 4);
        }
    };
    auto loadB = [&](int stage, int kt) {
#pragma unroll
        for (int i = 0; i < 2; i++) {
            int lin = tid + i * 256;
            int row = lin >> 2, c4 = lin & 3;
            cp_async16(sB_base + stage * STAGE_BYTES + (row * LDA + c4 * 4) * 4,
                       g_Wc + (size_t)(n0 + row) * IDIM + kt * BK + c4 * 4);
        }
    };

    loadA(0, 0); loadB(0, 0); CP_COMMIT();

    for (int kt = 0; kt < KTILES; ++kt) {
        const int cur = kt & 1;
        if (kt + 1 < KTILES) {
            loadA(cur ^ 1, kt + 1); loadB(cur ^ 1, kt + 1); CP_COMMIT();
            CP_WAIT(1);
        } else {
            CP_WAIT(0);
        }
        __syncthreads();

        const float* A = sA[cur];
        const float* B = sB[cur];
#pragma unroll
        for (int kf = 0; kf < 2; ++kf) {
            const int k = kf * 8;
            uint32_t a[2][4], bf[8][2];
#pragma unroll
            for (int mi = 0; mi < 2; mi++) {
                int r = wm * 32 + mi * 16 + g;
                a[mi][0] = __float_as_uint(A[r * LDA + k + tg]);
                a[mi][1] = __float_as_uint(A[(r + 8) * LDA + k + tg]);
                a[mi][2] = __float_as_uint(A[r * LDA + k + tg + 4]);
                a[mi][3] = __float_as_uint(A[(r + 8) * LDA + k + tg + 4]);
            }
#pragma unroll
            for (int ni = 0; ni < 8; ni++) {
                int cc = wn * 64 + ni * 8 + g;
                bf[ni][0] = __float_as_uint(B[cc * LDA + k + tg]);
                bf[ni][1] = __float_as_uint(B[cc * LDA + k + tg + 4]);
            }
#pragma unroll
            for (int mi = 0; mi < 2; mi++)
#pragma unroll
                for (int ni = 0; ni < 8; ni++) {
                    asm volatile(
                        "mma.sync.aligned.m16n8k8.row.col.f32.tf32.tf32.f32 "
                        "{%0,%1,%2,%3}, {%4,%5,%6,%7}, {%8,%9}, {%0,%1,%2,%3};"
                        : "+f"(c[mi][ni][0]), "+f"(c[mi][ni][1]),
                          "+f"(c[mi][ni][2]), "+f"(c[mi][ni][3])
                        : "r"(a[mi][0]), "r"(a[mi][1]), "r"(a[mi][2]), "r"(a[mi][3]),
                          "r"(bf[ni][0]), "r"(bf[ni][1]));
                }
        }
        __syncthreads();
    }

    // Epilogue: write u (row-major [MTOT, HDIM]) with float2 stores
#pragma unroll
    for (int mi = 0; mi < 2; mi++) {
#pragma unroll
        for (int ni = 0; ni < 8; ni++) {
            int r     = m0 + wm * 32 + mi * 16 + g;
            int cbase = n0 + wn * 64 + ni * 8 + 2 * tg;
            float2 v0 = make_float2(c[mi][ni][0], c[mi][ni][1]);
            float2 v1 = make_float2(c[mi][ni][2], c[mi][ni][3]);
            *reinterpret_cast<float2*>(g_u + (size_t)r * HDIM + cbase)       = v0;
            *reinterpret_cast<float2*>(g_u + (size_t)(r + 8) * HDIM + cbase) = v1;
        }
    }
}

// ---------------------------------------------------------------------------
// Kernel 3: sequential scan h = |u_t + hh*h| over s, one thread per (b,h).
// Register prefetch ring (depth 8) for MLP; fully coalesced (stride over s,
// consecutive threads hit consecutive h).
// ---------------------------------------------------------------------------
__global__ void scan_kernel(const float* __restrict__ hh) {
    const int ch = blockIdx.x * blockDim.x + threadIdx.x;  // b*2048 + h
    const float a = hh[ch & (HDIM - 1)];
    const float* p = g_u + ch;
    const size_t stride = (size_t)BATCH * HDIM;            // 131072

    float buf[8];
#pragma unroll
    for (int i = 0; i < 8; i++) buf[i] = p[(size_t)i * stride];

    float h = 0.0f;
    for (int s0 = 0; s0 < S_LEN; s0 += 8) {
#pragma unroll
        for (int i = 0; i < 8; i++) {
            float u = buf[i];
            int ns = s0 + 8 + i;
            if (ns < S_LEN) buf[i] = p[(size_t)ns * stride];
            h = fabsf(fmaf(a, h, u));
        }
    }
    g_h[ch] = h;
}

// ---------------------------------------------------------------------------
// Kernel 4: split-K output GEMM partials (deterministic, no atomics).
// grid = (ODIM/64 = 8, KSLICES = 16); each CTA computes a 64(b) x 64(o) tile
// over a K-range of 128, writes to g_part[kslice].
// ---------------------------------------------------------------------------
#define KSLICES 16

__global__ __launch_bounds__(256) void out_partial_kernel(const float* __restrict__ W_ho) {
    __shared__ float sh[64][65];
    __shared__ float sw[64][65];
    const int tid = threadIdx.x;
    const int tx = tid & 15, ty = tid >> 4;
    const int o0 = blockIdx.x * 64;
    const int ks = blockIdx.y;

    float acc[4][4];
#pragma unroll
    for (int i = 0; i < 4; i++)
#pragma unroll
        for (int j = 0; j < 4; j++) acc[i][j] = 0.0f;

    for (int kt = 0; kt < 2; kt++) {
        const int kbase = ks * 128 + kt * 64;
        // load tiles (coalesced rows of 64 floats)
#pragma unroll
        for (int i = 0; i < 16; i++) {
            int lin = tid + i * 256;
            int row = lin >> 6, col = lin & 63;
            sh[row][col] = g_h[(size_t)row * HDIM + kbase + col];
            sw[row][col] = W_ho[(size_t)(o0 + row) * HDIM + kbase + col];
        }
        __syncthreads();
#pragma unroll 8
        for (int k = 0; k < 64; k++) {
            float av[4], bv[4];
#pragma unroll
            for (int i = 0; i < 4; i++) av[i] = sh[ty * 4 + i][k];
#pragma unroll
            for (int j = 0; j < 4; j++) bv[j] = sw[tx * 4 + j][k];
#pragma unroll
            for (int i = 0; i < 4; i++)
#pragma unroll
                for (int j = 0; j < 4; j++) acc[i][j] = fmaf(av[i], bv[j], acc[i][j]);
        }
        __syncthreads();
    }

#pragma unroll
    for (int i = 0; i < 4; i++)
#pragma unroll
        for (int j = 0; j < 4; j++) {
            int b = ty * 4 + i;
            int o = o0 + tx * 4 + j;
            g_part[(size_t)ks * (BATCH * ODIM) + b * ODIM + o] = acc[i][j];
        }
}

// Kernel 5: reduce partials + bias -> Y
__global__ void out_reduce_kernel(const float* __restrict__ b_ho, float* __restrict__ Y) {
    int i = blockIdx.x * blockDim.x + threadIdx.x;  // < BATCH*ODIM
    float s = b_ho[i & (ODIM - 1)];
#pragma unroll
    for (int k = 0; k < KSLICES; k++) s += g_part[(size_t)k * (BATCH * ODIM) + i];
    Y[i] = s;
}

// ---------------------------------------------------------------------------
// Launch
// ---------------------------------------------------------------------------
extern "C" void kernel_launch(void* const* d_in, const int* in_sizes, int n_in,
                              void* d_out, int out_size) {
    const float* X    = (const float*)d_in[0];   // [1024,64,512]
    const float* W_ih = (const float*)d_in[1];   // [2048,512]
    const float* hh   = (const float*)d_in[2];   // [2048]
    const float* W_ho = (const float*)d_in[3];   // [512,2048]
    const float* b_ho = (const float*)d_in[4];   // [512]
    float* Y = (float*)d_out;                    // [64,512]

    // 1) tf32 rounding prepass
    cvtX_kernel<<<(MTOT * IDIM / 4) / 256, 256>>>((const float4*)X);
    cvtW_kernel<<<(HDIM * IDIM / 4) / 256, 256>>>((const float4*)W_ih);

    // 2) big GEMM u = Xc @ Wc^T
    dim3 ggrid(HDIM / BN, MTOT / BM);  // (16, 512)
    gemm_u_kernel<<<ggrid, 256>>>();

    // 3) sequential scan
    scan_kernel<<<(BATCH * HDIM) / 256, 256>>>(hh);

    // 4) output GEMM (split-K) + reduce
    dim3 ogrid(ODIM / 64, KSLICES);
    out_partial_kernel<<<ogrid, 256>>>(W_ho);
    out_reduce_kernel<<<(BATCH * ODIM) / 256, 256>>>(b_ho, Y);
}

// round 4
// speedup vs baseline: 1.7384x; 1.7384x over previous
#include <cuda_runtime.h>
#include <cuda_fp16.h>
#include <cstdint>

// Problem dims
#define S_LEN 1024
#define BATCH 64
#define IDIM  512
#define HDIM  2048
#define ODIM  512
#define MTOT  (S_LEN * BATCH)   // 65536

// ---------------------------------------------------------------------------
// Device scratch (no cudaMalloc allowed)
// ---------------------------------------------------------------------------
__device__ __half g_Xh[(size_t)MTOT * IDIM];        // 64 MB   fp16 X
__device__ __half g_Wh[(size_t)HDIM * IDIM];        // 2 MB    fp16 W_ih
__device__ __half g_uh[(size_t)MTOT * HDIM];        // 256 MB  u (fp16)
__device__ float  g_h [(size_t)BATCH * HDIM];       // 512 KB  h_final[b][h]
__device__ float  g_part[(size_t)16 * BATCH * ODIM];// 2 MB    split-K partials

// ---------------------------------------------------------------------------
// Helpers
// ---------------------------------------------------------------------------
__device__ __forceinline__ void cp_async16(uint32_t saddr, const void* gptr) {
    asm volatile("cp.async.cg.shared.global [%0], [%1], 16;\n"
                 :: "r"(saddr), "l"(gptr) : "memory");
}
#define CP_COMMIT() asm volatile("cp.async.commit_group;\n" ::: "memory")
#define CP_WAIT(N)  asm volatile("cp.async.wait_group %0;\n" :: "n"(N) : "memory")

struct alignas(16) H8 { __half2 a, b, c, d; };

// ---------------------------------------------------------------------------
// Kernels 1a/1b: fp32 -> fp16 conversion prepass
// ---------------------------------------------------------------------------
__global__ void cvtX_kernel(const float4* __restrict__ X) {
    int i = blockIdx.x * blockDim.x + threadIdx.x;   // over MTOT*IDIM/8
    float4 v0 = X[2 * i], v1 = X[2 * i + 1];
    H8 o;
    o.a = __floats2half2_rn(v0.x, v0.y);
    o.b = __floats2half2_rn(v0.z, v0.w);
    o.c = __floats2half2_rn(v1.x, v1.y);
    o.d = __floats2half2_rn(v1.z, v1.w);
    reinterpret_cast<H8*>(g_Xh)[i] = o;
}

__global__ void cvtW_kernel(const float4* __restrict__ W) {
    int i = blockIdx.x * blockDim.x + threadIdx.x;   // over HDIM*IDIM/8
    float4 v0 = W[2 * i], v1 = W[2 * i + 1];
    H8 o;
    o.a = __floats2half2_rn(v0.x, v0.y);
    o.b = __floats2half2_rn(v0.z, v0.w);
    o.c = __floats2half2_rn(v1.x, v1.y);
    o.d = __floats2half2_rn(v1.z, v1.w);
    reinterpret_cast<H8*>(g_Wh)[i] = o;
}

// ---------------------------------------------------------------------------
// Kernel 2: u = Xh @ Wh^T via mma.sync.m16n8k16.f32.f16.f16.f32
// CTA tile 128x128, BK=32 halves, 3-stage cp.async pipeline,
// 8 warps (4x2), warp tile 32x64, output stored as fp16.
// ---------------------------------------------------------------------------
#define BM 128
#define BN 128
#define BKH 32                     // halves per k-tile (64 B/row)
#define KTILES (IDIM / BKH)        // 16
#define NSTG 3
#define LDAH 40                    // padded row length in halves (80 B)
#define STAGE_HALFS (BM * LDAH)    // per-operand per-stage halves

__global__ __launch_bounds__(256, 2) void gemm_u_kernel() {
    __shared__ __half sA[NSTG][STAGE_HALFS];
    __shared__ __half sB[NSTG][STAGE_HALFS];

    const int tid  = threadIdx.x;
    const int lane = tid & 31;
    const int warp = tid >> 5;
    const int wm   = warp >> 1;   // 0..3
    const int wn   = warp & 1;    // 0..1
    const int g    = lane >> 2;   // 0..7
    const int tg   = lane & 3;    // 0..3

    const int m0 = blockIdx.y * BM;
    const int n0 = blockIdx.x * BN;

    const uint32_t sA_base = (uint32_t)__cvta_generic_to_shared(&sA[0][0]);
    const uint32_t sB_base = (uint32_t)__cvta_generic_to_shared(&sB[0][0]);

    float c[2][8][4];
#pragma unroll
    for (int mi = 0; mi < 2; mi++)
#pragma unroll
        for (int ni = 0; ni < 8; ni++)
#pragma unroll
            for (int r = 0; r < 4; r++) c[mi][ni][r] = 0.0f;

    // loaders: 128 rows x 32 halves = 128 rows x 4 chunks(16B) = 512 chunks
    // per operand; 256 threads -> 2 chunks each per operand.
    auto loadAB = [&](int stage, int kt) {
#pragma unroll
        for (int i = 0; i < 2; i++) {
            int lin = tid + i * 256;
            int row = lin >> 2, c16 = lin & 3;
            cp_async16(sA_base + (stage * STAGE_HALFS + row * LDAH + c16 * 8) * 2,
                       g_Xh + (size_t)(m0 + row) * IDIM + kt * BKH + c16 * 8);
            cp_async16(sB_base + (stage * STAGE_HALFS + row * LDAH + c16 * 8) * 2,
                       g_Wh + (size_t)(n0 + row) * IDIM + kt * BKH + c16 * 8);
        }
    };

    loadAB(0, 0); CP_COMMIT();
    loadAB(1, 1); CP_COMMIT();

    for (int kt = 0; kt < KTILES; ++kt) {
        if (kt < KTILES - 1) { CP_WAIT(1); } else { CP_WAIT(0); }
        __syncthreads();

        // prefetch stage kt+2 (overwrites stage (kt-1)%3 — safe after barrier)
        if (kt + 2 < KTILES) { loadAB((kt + 2) % NSTG, kt + 2); CP_COMMIT(); }

        const __half* A = sA[kt % NSTG];
        const __half* B = sB[kt % NSTG];
#pragma unroll
        for (int kf = 0; kf < 2; ++kf) {
            const int k = kf * 16;
            uint32_t a[2][4], bf[8][2];
#pragma unroll
            for (int mi = 0; mi < 2; mi++) {
                int r = wm * 32 + mi * 16 + g;
                a[mi][0] = *(const uint32_t*)&A[r * LDAH + k + tg * 2];
                a[mi][1] = *(const uint32_t*)&A[(r + 8) * LDAH + k + tg * 2];
                a[mi][2] = *(const uint32_t*)&A[r * LDAH + k + 8 + tg * 2];
                a[mi][3] = *(const uint32_t*)&A[(r + 8) * LDAH + k + 8 + tg * 2];
            }
#pragma unroll
            for (int ni = 0; ni < 8; ni++) {
                int cc = wn * 64 + ni * 8 + g;
                bf[ni][0] = *(const uint32_t*)&B[cc * LDAH + k + tg * 2];
                bf[ni][1] = *(const uint32_t*)&B[cc * LDAH + k + 8 + tg * 2];
            }
#pragma unroll
            for (int mi = 0; mi < 2; mi++)
#pragma unroll
                for (int ni = 0; ni < 8; ni++) {
                    asm volatile(
                        "mma.sync.aligned.m16n8k16.row.col.f32.f16.f16.f32 "
                        "{%0,%1,%2,%3}, {%4,%5,%6,%7}, {%8,%9}, {%0,%1,%2,%3};"
                        : "+f"(c[mi][ni][0]), "+f"(c[mi][ni][1]),
                          "+f"(c[mi][ni][2]), "+f"(c[mi][ni][3])
                        : "r"(a[mi][0]), "r"(a[mi][1]), "r"(a[mi][2]), "r"(a[mi][3]),
                          "r"(bf[ni][0]), "r"(bf[ni][1]));
                }
        }
        __syncthreads();
    }

    // Epilogue: u stored as fp16 (half2 per thread per frag-row)
#pragma unroll
    for (int mi = 0; mi < 2; mi++) {
#pragma unroll
        for (int ni = 0; ni < 8; ni++) {
            int r     = m0 + wm * 32 + mi * 16 + g;
            int cbase = n0 + wn * 64 + ni * 8 + 2 * tg;
            __half2 v0 = __floats2half2_rn(c[mi][ni][0], c[mi][ni][1]);
            __half2 v1 = __floats2half2_rn(c[mi][ni][2], c[mi][ni][3]);
            *reinterpret_cast<__half2*>(g_uh + (size_t)r * HDIM + cbase)       = v0;
            *reinterpret_cast<__half2*>(g_uh + (size_t)(r + 8) * HDIM + cbase) = v1;
        }
    }
}

// ---------------------------------------------------------------------------
// Kernel 3: sequential scan h = |u_t + hh*h|, fp16 u, 2 channels/thread.
// ---------------------------------------------------------------------------
__global__ void scan_kernel(const float* __restrict__ hh) {
    const int ch2 = blockIdx.x * blockDim.x + threadIdx.x;   // half2 index
    const int hpair = (2 * ch2) & (HDIM - 1);
    const float a0 = hh[hpair];
    const float a1 = hh[hpair + 1];
    const __half2* p = reinterpret_cast<const __half2*>(g_uh) + ch2;
    const size_t stride = (size_t)BATCH * HDIM / 2;          // 65536 half2s

    __half2 buf[8];
#pragma unroll
    for (int i = 0; i < 8; i++) buf[i] = p[(size_t)i * stride];

    float h0 = 0.0f, h1 = 0.0f;
    for (int s0 = 0; s0 < S_LEN; s0 += 8) {
#pragma unroll
        for (int i = 0; i < 8; i++) {
            float2 u = __half22float2(buf[i]);
            int ns = s0 + 8 + i;
            if (ns < S_LEN) buf[i] = p[(size_t)ns * stride];
            h0 = fabsf(fmaf(a0, h0, u.x));
            h1 = fabsf(fmaf(a1, h1, u.y));
        }
    }
    *reinterpret_cast<float2*>(g_h + 2 * ch2) = make_float2(h0, h1);
}

// ---------------------------------------------------------------------------
// Kernel 4/5: split-K output GEMM + reduce
// ---------------------------------------------------------------------------
#define KSLICES 16

__global__ __launch_bounds__(256) void out_partial_kernel(const float* __restrict__ W_ho) {
    __shared__ float sh[64][65];
    __shared__ float sw[64][65];
    const int tid = threadIdx.x;
    const int tx = tid & 15, ty = tid >> 4;
    const int o0 = blockIdx.x * 64;
    const int ks = blockIdx.y;

    float acc[4][4];
#pragma unroll
    for (int i = 0; i < 4; i++)
#pragma unroll
        for (int j = 0; j < 4; j++) acc[i][j] = 0.0f;

    for (int kt = 0; kt < 2; kt++) {
        const int kbase = ks * 128 + kt * 64;
#pragma unroll
        for (int i = 0; i < 16; i++) {
            int lin = tid + i * 256;
            int row = lin >> 6, col = lin & 63;
            sh[row][col] = g_h[(size_t)row * HDIM + kbase + col];
            sw[row][col] = W_ho[(size_t)(o0 + row) * HDIM + kbase + col];
        }
        __syncthreads();
#pragma unroll 8
        for (int k = 0; k < 64; k++) {
            float av[4], bv[4];
#pragma unroll
            for (int i = 0; i < 4; i++) av[i] = sh[ty * 4 + i][k];
#pragma unroll
            for (int j = 0; j < 4; j++) bv[j] = sw[tx * 4 + j][k];
#pragma unroll
            for (int i = 0; i < 4; i++)
#pragma unroll
                for (int j = 0; j < 4; j++) acc[i][j] = fmaf(av[i], bv[j], acc[i][j]);
        }
        __syncthreads();
    }

#pragma unroll
    for (int i = 0; i < 4; i++)
#pragma unroll
        for (int j = 0; j < 4; j++) {
            int b = ty * 4 + i;
            int o = o0 + tx * 4 + j;
            g_part[(size_t)ks * (BATCH * ODIM) + b * ODIM + o] = acc[i][j];
        }
}

__global__ void out_reduce_kernel(const float* __restrict__ b_ho, float* __restrict__ Y) {
    int i = blockIdx.x * blockDim.x + threadIdx.x;
    float s = b_ho[i & (ODIM - 1)];
#pragma unroll
    for (int k = 0; k < KSLICES; k++) s += g_part[(size_t)k * (BATCH * ODIM) + i];
    Y[i] = s;
}

// ---------------------------------------------------------------------------
// Launch
// ---------------------------------------------------------------------------
extern "C" void kernel_launch(void* const* d_in, const int* in_sizes, int n_in,
                              void* d_out, int out_size) {
    const float* X    = (const float*)d_in[0];   // [1024,64,512]
    const float* W_ih = (const float*)d_in[1];   // [2048,512]
    const float* hh   = (const float*)d_in[2];   // [2048]
    const float* W_ho = (const float*)d_in[3];   // [512,2048]
    const float* b_ho = (const float*)d_in[4];   // [512]
    float* Y = (float*)d_out;                    // [64,512]

    // 1) fp16 conversion prepass
    cvtX_kernel<<<(MTOT * IDIM / 8) / 256, 256>>>((const float4*)X);
    cvtW_kernel<<<(HDIM * IDIM / 8) / 256, 256>>>((const float4*)W_ih);

    // 2) big GEMM u = Xh @ Wh^T (fp16 mma, fp32 accum)
    dim3 ggrid(HDIM / BN, MTOT / BM);  // (16, 512) x-major: N-tiles share A in L2
    gemm_u_kernel<<<ggrid, 256>>>();

    // 3) sequential scan (2 channels per thread, half2 loads)
    scan_kernel<<<(BATCH * HDIM / 2) / 256, 256>>>(hh);

    // 4) output GEMM (split-K) + reduce
    dim3 ogrid(ODIM / 64, KSLICES);
    out_partial_kernel<<<ogrid, 256>>>(W_ho);
    out_reduce_kernel<<<(BATCH * ODIM) / 256, 256>>>(b_ho, Y);
}

// round 5
// speedup vs baseline: 1.8040x; 1.0377x over previous
#include <cuda_runtime.h>
#include <cuda_fp16.h>
#include <cstdint>

// Problem dims
#define S_LEN 1024
#define BATCH 64
#define IDIM  512
#define HDIM  2048
#define ODIM  512
#define MTOT  (S_LEN * BATCH)   // 65536

// ---------------------------------------------------------------------------
// Device scratch (no cudaMalloc allowed)
// ---------------------------------------------------------------------------
__device__ __half g_Xh[(size_t)MTOT * IDIM];        // 64 MB   fp16 X
__device__ __half g_Wh[(size_t)HDIM * IDIM];        // 2 MB    fp16 W_ih
__device__ __half g_uh[(size_t)MTOT * HDIM];        // 256 MB  u (fp16)
__device__ float  g_h [(size_t)BATCH * HDIM];       // 512 KB  h_final[b][h]
__device__ float  g_part[(size_t)16 * BATCH * ODIM];// 2 MB    split-K partials

// ---------------------------------------------------------------------------
// Helpers
// ---------------------------------------------------------------------------
__device__ __forceinline__ void cp_async16(uint32_t saddr, const void* gptr) {
    asm volatile("cp.async.cg.shared.global [%0], [%1], 16;\n"
                 :: "r"(saddr), "l"(gptr) : "memory");
}
#define CP_COMMIT() asm volatile("cp.async.commit_group;\n" ::: "memory")
#define CP_WAIT(N)  asm volatile("cp.async.wait_group %0;\n" :: "n"(N) : "memory")

struct alignas(16) H8 { __half2 a, b, c, d; };

// ---------------------------------------------------------------------------
// Kernels 1a/1b: fp32 -> fp16 conversion prepass
// ---------------------------------------------------------------------------
__global__ void cvtX_kernel(const float4* __restrict__ X) {
    int i = blockIdx.x * blockDim.x + threadIdx.x;   // over MTOT*IDIM/8
    float4 v0 = X[2 * i], v1 = X[2 * i + 1];
    H8 o;
    o.a = __floats2half2_rn(v0.x, v0.y);
    o.b = __floats2half2_rn(v0.z, v0.w);
    o.c = __floats2half2_rn(v1.x, v1.y);
    o.d = __floats2half2_rn(v1.z, v1.w);
    reinterpret_cast<H8*>(g_Xh)[i] = o;
}

__global__ void cvtW_kernel(const float4* __restrict__ W) {
    int i = blockIdx.x * blockDim.x + threadIdx.x;   // over HDIM*IDIM/8
    float4 v0 = W[2 * i], v1 = W[2 * i + 1];
    H8 o;
    o.a = __floats2half2_rn(v0.x, v0.y);
    o.b = __floats2half2_rn(v0.z, v0.w);
    o.c = __floats2half2_rn(v1.x, v1.y);
    o.d = __floats2half2_rn(v1.z, v1.w);
    reinterpret_cast<H8*>(g_Wh)[i] = o;
}

// ---------------------------------------------------------------------------
// Kernel 2: u = Xh @ Wh^T via mma.sync.m16n8k16.f32.f16.f16.f32
// CTA tile 128x128, BK=32 halves, 3-stage cp.async pipeline,
// 8 warps (4x2), warp tile 32x64, output stored as fp16.
// ---------------------------------------------------------------------------
#define BM 128
#define BN 128
#define BKH 32                     // halves per k-tile (64 B/row)
#define KTILES (IDIM / BKH)        // 16
#define NSTG 3
#define LDAH 40                    // padded row length in halves (80 B)
#define STAGE_HALFS (BM * LDAH)    // per-operand per-stage halves

__global__ __launch_bounds__(256, 2) void gemm_u_kernel() {
    __shared__ __half sA[NSTG][STAGE_HALFS];
    __shared__ __half sB[NSTG][STAGE_HALFS];

    const int tid  = threadIdx.x;
    const int lane = tid & 31;
    const int warp = tid >> 5;
    const int wm   = warp >> 1;   // 0..3
    const int wn   = warp & 1;    // 0..1
    const int g    = lane >> 2;   // 0..7
    const int tg   = lane & 3;    // 0..3

    const int m0 = blockIdx.y * BM;
    const int n0 = blockIdx.x * BN;

    const uint32_t sA_base = (uint32_t)__cvta_generic_to_shared(&sA[0][0]);
    const uint32_t sB_base = (uint32_t)__cvta_generic_to_shared(&sB[0][0]);

    float c[2][8][4];
#pragma unroll
    for (int mi = 0; mi < 2; mi++)
#pragma unroll
        for (int ni = 0; ni < 8; ni++)
#pragma unroll
            for (int r = 0; r < 4; r++) c[mi][ni][r] = 0.0f;

    auto loadAB = [&](int stage, int kt) {
#pragma unroll
        for (int i = 0; i < 2; i++) {
            int lin = tid + i * 256;
            int row = lin >> 2, c16 = lin & 3;
            cp_async16(sA_base + (stage * STAGE_HALFS + row * LDAH + c16 * 8) * 2,
                       g_Xh + (size_t)(m0 + row) * IDIM + kt * BKH + c16 * 8);
            cp_async16(sB_base + (stage * STAGE_HALFS + row * LDAH + c16 * 8) * 2,
                       g_Wh + (size_t)(n0 + row) * IDIM + kt * BKH + c16 * 8);
        }
    };

    loadAB(0, 0); CP_COMMIT();
    loadAB(1, 1); CP_COMMIT();

    for (int kt = 0; kt < KTILES; ++kt) {
        if (kt < KTILES - 1) { CP_WAIT(1); } else { CP_WAIT(0); }
        __syncthreads();

        if (kt + 2 < KTILES) { loadAB((kt + 2) % NSTG, kt + 2); CP_COMMIT(); }

        const __half* A = sA[kt % NSTG];
        const __half* B = sB[kt % NSTG];
#pragma unroll
        for (int kf = 0; kf < 2; ++kf) {
            const int k = kf * 16;
            uint32_t a[2][4], bf[8][2];
#pragma unroll
            for (int mi = 0; mi < 2; mi++) {
                int r = wm * 32 + mi * 16 + g;
                a[mi][0] = *(const uint32_t*)&A[r * LDAH + k + tg * 2];
                a[mi][1] = *(const uint32_t*)&A[(r + 8) * LDAH + k + tg * 2];
                a[mi][2] = *(const uint32_t*)&A[r * LDAH + k + 8 + tg * 2];
                a[mi][3] = *(const uint32_t*)&A[(r + 8) * LDAH + k + 8 + tg * 2];
            }
#pragma unroll
            for (int ni = 0; ni < 8; ni++) {
                int cc = wn * 64 + ni * 8 + g;
                bf[ni][0] = *(const uint32_t*)&B[cc * LDAH + k + tg * 2];
                bf[ni][1] = *(const uint32_t*)&B[cc * LDAH + k + 8 + tg * 2];
            }
#pragma unroll
            for (int mi = 0; mi < 2; mi++)
#pragma unroll
                for (int ni = 0; ni < 8; ni++) {
                    asm volatile(
                        "mma.sync.aligned.m16n8k16.row.col.f32.f16.f16.f32 "
                        "{%0,%1,%2,%3}, {%4,%5,%6,%7}, {%8,%9}, {%0,%1,%2,%3};"
                        : "+f"(c[mi][ni][0]), "+f"(c[mi][ni][1]),
                          "+f"(c[mi][ni][2]), "+f"(c[mi][ni][3])
                        : "r"(a[mi][0]), "r"(a[mi][1]), "r"(a[mi][2]), "r"(a[mi][3]),
                          "r"(bf[ni][0]), "r"(bf[ni][1]));
                }
        }
        __syncthreads();
    }

#pragma unroll
    for (int mi = 0; mi < 2; mi++) {
#pragma unroll
        for (int ni = 0; ni < 8; ni++) {
            int r     = m0 + wm * 32 + mi * 16 + g;
            int cbase = n0 + wn * 64 + ni * 8 + 2 * tg;
            __half2 v0 = __floats2half2_rn(c[mi][ni][0], c[mi][ni][1]);
            __half2 v1 = __floats2half2_rn(c[mi][ni][2], c[mi][ni][3]);
            *reinterpret_cast<__half2*>(g_uh + (size_t)r * HDIM + cbase)       = v0;
            *reinterpret_cast<__half2*>(g_uh + (size_t)(r + 8) * HDIM + cbase) = v1;
        }
    }
}

// ---------------------------------------------------------------------------
// Kernel 3: sequential scan h = |u_t + hh*h|, fp16 u, 2 channels/thread.
// Depth-16 register prefetch ring: 65536 thr x 16 x 4B = 4 MB in flight
// (> BW x DRAM-latency ~2.6 MB) -> HBM-saturating despite grid of 256 CTAs.
// ---------------------------------------------------------------------------
#define SCAN_DEPTH 16

__global__ void scan_kernel(const float* __restrict__ hh) {
    const int ch2 = blockIdx.x * blockDim.x + threadIdx.x;   // half2 index
    const int hpair = (2 * ch2) & (HDIM - 1);
    const float a0 = hh[hpair];
    const float a1 = hh[hpair + 1];
    const __half2* p = reinterpret_cast<const __half2*>(g_uh) + ch2;
    const size_t stride = (size_t)BATCH * HDIM / 2;          // 65536 half2s

    __half2 buf[SCAN_DEPTH];
#pragma unroll
    for (int i = 0; i < SCAN_DEPTH; i++) buf[i] = p[(size_t)i * stride];

    float h0 = 0.0f, h1 = 0.0f;
    for (int s0 = 0; s0 < S_LEN; s0 += SCAN_DEPTH) {
#pragma unroll
        for (int i = 0; i < SCAN_DEPTH; i++) {
            float2 u = __half22float2(buf[i]);
            int ns = s0 + SCAN_DEPTH + i;
            if (ns < S_LEN) buf[i] = p[(size_t)ns * stride];
            h0 = fabsf(fmaf(a0, h0, u.x));
            h1 = fabsf(fmaf(a1, h1, u.y));
        }
    }
    *reinterpret_cast<float2*>(g_h + 2 * ch2) = make_float2(h0, h1);
}

// ---------------------------------------------------------------------------
// Kernel 4/5: split-K output GEMM + reduce
// ---------------------------------------------------------------------------
#define KSLICES 16

__global__ __launch_bounds__(256) void out_partial_kernel(const float* __restrict__ W_ho) {
    __shared__ float sh[64][65];
    __shared__ float sw[64][65];
    const int tid = threadIdx.x;
    const int tx = tid & 15, ty = tid >> 4;
    const int o0 = blockIdx.x * 64;
    const int ks = blockIdx.y;

    float acc[4][4];
#pragma unroll
    for (int i = 0; i < 4; i++)
#pragma unroll
        for (int j = 0; j < 4; j++) acc[i][j] = 0.0f;

    for (int kt = 0; kt < 2; kt++) {
        const int kbase = ks * 128 + kt * 64;
#pragma unroll
        for (int i = 0; i < 16; i++) {
            int lin = tid + i * 256;
            int row = lin >> 6, col = lin & 63;
            sh[row][col] = g_h[(size_t)row * HDIM + kbase + col];
            sw[row][col] = W_ho[(size_t)(o0 + row) * HDIM + kbase + col];
        }
        __syncthreads();
#pragma unroll 8
        for (int k = 0; k < 64; k++) {
            float av[4], bv[4];
#pragma unroll
            for (int i = 0; i < 4; i++) av[i] = sh[ty * 4 + i][k];
#pragma unroll
            for (int j = 0; j < 4; j++) bv[j] = sw[tx * 4 + j][k];
#pragma unroll
            for (int i = 0; i < 4; i++)
#pragma unroll
                for (int j = 0; j < 4; j++) acc[i][j] = fmaf(av[i], bv[j], acc[i][j]);
        }
        __syncthreads();
    }

#pragma unroll
    for (int i = 0; i < 4; i++)
#pragma unroll
        for (int j = 0; j < 4; j++) {
            int b = ty * 4 + i;
            int o = o0 + tx * 4 + j;
            g_part[(size_t)ks * (BATCH * ODIM) + b * ODIM + o] = acc[i][j];
        }
}

__global__ void out_reduce_kernel(const float* __restrict__ b_ho, float* __restrict__ Y) {
    int i = blockIdx.x * blockDim.x + threadIdx.x;
    float s = b_ho[i & (ODIM - 1)];
#pragma unroll
    for (int k = 0; k < KSLICES; k++) s += g_part[(size_t)k * (BATCH * ODIM) + i];
    Y[i] = s;
}

// ---------------------------------------------------------------------------
// Launch
// ---------------------------------------------------------------------------
extern "C" void kernel_launch(void* const* d_in, const int* in_sizes, int n_in,
                              void* d_out, int out_size) {
    const float* X    = (const float*)d_in[0];   // [1024,64,512]
    const float* W_ih = (const float*)d_in[1];   // [2048,512]
    const float* hh   = (const float*)d_in[2];   // [2048]
    const float* W_ho = (const float*)d_in[3];   // [512,2048]
    const float* b_ho = (const float*)d_in[4];   // [512]
    float* Y = (float*)d_out;                    // [64,512]

    // 1) fp16 conversion prepass
    cvtX_kernel<<<(MTOT * IDIM / 8) / 256, 256>>>((const float4*)X);
    cvtW_kernel<<<(HDIM * IDIM / 8) / 256, 256>>>((const float4*)W_ih);

    // 2) big GEMM u = Xh @ Wh^T (fp16 mma, fp32 accum)
    dim3 ggrid(HDIM / BN, MTOT / BM);  // (16, 512) x-major: N-tiles share A in L2
    gemm_u_kernel<<<ggrid, 256>>>();

    // 3) sequential scan (2 channels per thread, depth-16 prefetch ring)
    scan_kernel<<<(BATCH * HDIM / 2) / 256, 256>>>(hh);

    // 4) output GEMM (split-K) + reduce
    dim3 ogrid(ODIM / 64, KSLICES);
    out_partial_kernel<<<ogrid, 256>>>(W_ho);
    out_reduce_kernel<<<(BATCH * ODIM) / 256, 256>>>(b_ho, Y);
}